// round 14
// baseline (speedup 1.0000x reference)
#include <cuda_runtime.h>
#include <math.h>

// Problem constants (fixed by setup_inputs)
#define Bc 128
#define Nc 96
#define Dc 3072
#define Kc 10
#define KP 5                       // k-pairs (Kc/2)
#define THREADS 896
#define WARPS 28
#define GRID1 148
#define WSLOTS (GRID1*WARPS)       // 4144
#define CHUNKS 8
#define CHUNK_D (Dc/CHUNKS)        // 384
#define ITERS (CHUNK_D/128)        // 3
#define NPAIRS (Nc/2)              // 48
#define NUNITS (NPAIRS*Bc*CHUNKS)  // 49152
#define PARTS 4                    // partial lanes after 3-round butterfly
#define SMEM_BYTES (KP*Dc*8)       // 122880

typedef unsigned long long u64;

// partial packed logits: [rid][kp][32]  (rid = b*Nc + n; 32 = chunk*4 + part)
__device__ u64   g_plog[(size_t)Bc*Nc*KP*32];
__device__ float g_l1[Bc*Nc];
__device__ float g_l2[Bc*Nc];
__device__ float g_part[Bc];

// ---- packed f32x2 ops (Blackwell; add/sub/mul/fma only) ----
#define FMA2(d, a, b, c) \
    asm("fma.rn.f32x2 %0, %1, %2, %3;" : "=l"(d) : "l"(a), "l"(b), "l"(c))
#define ADD2(d, a, b) \
    asm("add.rn.f32x2 %0, %1, %2;" : "=l"(d) : "l"(a), "l"(b))
// scalar saturating add: clip(a+b, 0, 1) in one FADD.SAT
#define ADDSAT(d, a, b) \
    asm("add.rn.sat.f32 %0, %1, %2;" : "=f"(d) : "f"(a), "f"(b))

__device__ __forceinline__ u64 pack2(float lo, float hi) {
    u64 r;
    asm("mov.b64 %0, {%1, %2};" : "=l"(r) : "f"(lo), "f"(hi));
    return r;
}
__device__ __forceinline__ void unpack2(float& lo, float& hi, u64 v) {
    asm("mov.b64 {%0, %1}, %2;" : "=f"(lo), "=f"(hi) : "l"(v));
}

__global__ __launch_bounds__(THREADS, 1)
void logits_kernel(const float* __restrict__ imgs,
                   const float* __restrict__ deltas,
                   const float* __restrict__ Wm)
{
    extern __shared__ u64 sW2[];   // [KP][Dc]: sW2[kp*Dc+d] = (W[d][2kp], W[d][2kp+1])

    // Wm is [D][10] row-major: each row = 5 contiguous u64 k-pairs.
    const u64* Wm64 = (const u64*)Wm;
    for (int idx = threadIdx.x; idx < Dc*KP; idx += THREADS) {
        int d  = idx / KP;
        int kp = idx - d*KP;
        sW2[kp*Dc + d] = Wm64[idx];
    }
    __syncthreads();

    const int warp  = threadIdx.x >> 5;
    const int lane  = threadIdx.x & 31;
    const int wslot = blockIdx.x*WARPS + warp;

    for (int u = wslot; u < NUNITS; u += WSLOTS) {
        const int chunk = u & (CHUNKS-1);
        const int t     = u >> 3;
        const int b     = t & (Bc-1);
        const int n0    = (t >> 7) << 1;

        const float4* img4 = (const float4*)(imgs + (size_t)b*Dc) + lane;
        const float4* dp0  = (const float4*)(deltas + ((size_t)n0*Bc + b)*Dc) + lane;
        const float4* dp1  = (const float4*)(deltas + ((size_t)(n0+1)*Bc + b)*Dc) + lane;

        u64 acc0[KP], acc1[KP];
#pragma unroll
        for (int kp = 0; kp < KP; kp++) { acc0[kp] = 0ULL; acc1[kp] = 0ULL; }

#pragma unroll
        for (int it = 0; it < ITERS; it++) {
            const int e = chunk*(CHUNK_D/4) + it*32;   // float4 offset (lane in ptr)
            float4 xi  = __ldg(img4 + e);
            float4 dd0 = __ldcs(dp0 + e);
            float4 dd1 = __ldcs(dp1 + e);

            // clip once per element, duplicate into both packed halves
            u64 x0[4], x1[4];
            {
                float a0,a1,a2,a3;
                ADDSAT(a0, xi.x, dd0.x); ADDSAT(a1, xi.y, dd0.y);
                ADDSAT(a2, xi.z, dd0.z); ADDSAT(a3, xi.w, dd0.w);
                x0[0]=pack2(a0,a0); x0[1]=pack2(a1,a1);
                x0[2]=pack2(a2,a2); x0[3]=pack2(a3,a3);
            }
            {
                float a0,a1,a2,a3;
                ADDSAT(a0, xi.x, dd1.x); ADDSAT(a1, xi.y, dd1.y);
                ADDSAT(a2, xi.z, dd1.z); ADDSAT(a3, xi.w, dd1.w);
                x1[0]=pack2(a0,a0); x1[1]=pack2(a1,a1);
                x1[2]=pack2(a2,a2); x1[3]=pack2(a3,a3);
            }

            const int d0 = (e + lane)*4;   // element index of this lane's 4 d's
#pragma unroll
            for (int kp = 0; kp < KP; kp++) {
                const ulonglong2* wp = (const ulonglong2*)(sW2 + (size_t)kp*Dc + d0);
                ulonglong2 wa = wp[0];     // W pairs for d0, d0+1
                ulonglong2 wb = wp[1];     // W pairs for d0+2, d0+3
                FMA2(acc0[kp], x0[0], wa.x, acc0[kp]);
                FMA2(acc0[kp], x0[1], wa.y, acc0[kp]);
                FMA2(acc0[kp], x0[2], wb.x, acc0[kp]);
                FMA2(acc0[kp], x0[3], wb.y, acc0[kp]);
                FMA2(acc1[kp], x1[0], wa.x, acc1[kp]);
                FMA2(acc1[kp], x1[1], wa.y, acc1[kp]);
                FMA2(acc1[kp], x1[2], wb.x, acc1[kp]);
                FMA2(acc1[kp], x1[3], wb.y, acc1[kp]);
            }
        }

        // 3-round packed butterfly (masks 16,8,4): every lane = its mod-4 group sum
#pragma unroll
        for (int kp = 0; kp < KP; kp++) {
#pragma unroll
            for (int m = 16; m >= 4; m >>= 1) {
                u64 o0 = __shfl_xor_sync(0xFFFFFFFFu, acc0[kp], m);
                u64 o1 = __shfl_xor_sync(0xFFFFFFFFu, acc1[kp], m);
                ADD2(acc0[kp], acc0[kp], o0);
                ADD2(acc1[kp], acc1[kp], o1);
            }
        }

        if (lane < PARTS) {
            const int rid0 = b*Nc + n0;
            u64* p0 = g_plog + ((size_t)rid0*KP)*32       + chunk*PARTS + lane;
            u64* p1 = g_plog + ((size_t)(rid0+1)*KP)*32   + chunk*PARTS + lane;
#pragma unroll
            for (int kp = 0; kp < KP; kp++) {
                p0[kp*32] = acc0[kp];
                p1[kp*32] = acc1[kp];
            }
        }
    }
}

// Reduce 32 partials per (rid, kp), add bias, compute loss1/loss2.
__global__ void loss_kernel(const float* __restrict__ bias,
                            const int* __restrict__ labels)
{
    const int rid = blockIdx.x*blockDim.x + threadIdx.x;   // rid = b*Nc + n
    if (rid >= Bc*Nc) return;
    const int b = rid / Nc;

    float lg[Kc];
#pragma unroll
    for (int kp = 0; kp < KP; kp++) {
        const ulonglong2* p = (const ulonglong2*)(g_plog + ((size_t)rid*KP + kp)*32);
        u64 s = 0ULL;
#pragma unroll
        for (int tix = 0; tix < 16; tix++) {
            ulonglong2 v = __ldg(p + tix);
            ADD2(s, s, v.x);
            ADD2(s, s, v.y);
        }
        float lo, hi;
        unpack2(lo, hi, s);
        lg[2*kp]   = lo + __ldg(bias + 2*kp);
        lg[2*kp+1] = hi + __ldg(bias + 2*kp + 1);
    }

    // argmax (first occurrence, matches top_k tie rule)
    float m = lg[0]; int t1 = 0;
#pragma unroll
    for (int k = 1; k < Kc; k++)
        if (lg[k] > m) { m = lg[k]; t1 = k; }

    float s = 0.0f;
#pragma unroll
    for (int k = 0; k < Kc; k++) s += expf(lg[k] - m);
    float lse = m + logf(s);

    int lab = __ldg(labels + b);
    float logit_lab = lg[0];
#pragma unroll
    for (int k = 1; k < Kc; k++)
        if (k == lab) logit_lab = lg[k];
    float loss1 = lse - logit_lab;

    // second-best (first occurrence among k != t1)
    float m2 = -INFINITY; int t2 = 0;
#pragma unroll
    for (int k = 0; k < Kc; k++)
        if (k != t1 && lg[k] > m2) { m2 = lg[k]; t2 = k; }
    float logit_t2 = lg[0];
#pragma unroll
    for (int k = 1; k < Kc; k++)
        if (k == t2) logit_t2 = lg[k];

    float loss2 = (t1 == lab) ? (lse - logit_t2) : -10000.0f;

    g_l1[rid] = loss1;
    g_l2[rid] = loss2;
}

// Per-batch-row stable rank-select (replicates stable argsort exactly)
__global__ void select_kernel(const int* __restrict__ indp)
{
    __shared__ float sd[Nc];
    __shared__ float sl1[Nc];
    __shared__ float sSel;

    const int b = blockIdx.x;
    const int j = threadIdx.x;   // 0..95

    float l1v = 0.0f, l2v = 0.0f, dv = 0.0f;
    if (j < Nc) {
        l1v = g_l1[b*Nc + j];
        l2v = g_l2[b*Nc + j];
        dv  = l1v - l2v;
        sd[j]  = dv;
        sl1[j] = l1v;
    }
    __syncthreads();

    const int ind = __ldg(indp);
    if (j < Nc) {
        int cnt = 0;
        for (int i = 0; i < Nc; i++) {
            float di = sd[i];
            cnt += (di < dv) || (di == dv && i < j);
        }
        if (cnt == ind) sSel = l2v;   // exactly one j satisfies this
    }
    __syncthreads();

    if (j == 0) {
        float ssum = 0.0f;
        for (int i = 0; i < Nc; i++) ssum += sl1[i];
        g_part[b] = ssum / (float)Nc - sSel;
    }
}

__global__ void reduce_kernel(float* __restrict__ out)
{
    if (threadIdx.x == 0) {
        float a = 0.0f;
#pragma unroll
        for (int i = 0; i < Bc; i++) a += g_part[i];
        out[0] = a / (float)Bc;
    }
}

extern "C" void kernel_launch(void* const* d_in, const int* in_sizes, int n_in,
                              void* d_out, int out_size)
{
    const float* imgs   = (const float*)d_in[0];
    const float* deltas = (const float*)d_in[1];
    const float* Wm     = (const float*)d_in[2];
    const float* bias   = (const float*)d_in[3];
    const int*   labels = (const int*)d_in[4];
    const int*   indp   = (const int*)d_in[5];
    float* out = (float*)d_out;

    cudaFuncSetAttribute(logits_kernel,
                         cudaFuncAttributeMaxDynamicSharedMemorySize, SMEM_BYTES);

    logits_kernel<<<GRID1, THREADS, SMEM_BYTES>>>(imgs, deltas, Wm);
    loss_kernel<<<(Bc*Nc + 255)/256, 256>>>(bias, labels);
    select_kernel<<<Bc, Nc>>>(indp);
    reduce_kernel<<<1, 32>>>(out);
}

// round 15
// speedup vs baseline: 1.4879x; 1.4879x over previous
#include <cuda_runtime.h>
#include <math.h>

// Problem constants (fixed by setup_inputs)
#define Bc 128
#define Nc 96
#define Dc 3072
#define Kc 10
#define RPW 2
#define WARPS 24
#define THREADS (WARPS*32)               // 768
#define NUNITS (Bc*(Nc/RPW))             // 6144
#define GRID1 128
#define WSLOTS (GRID1*WARPS)             // 3072  -> exactly 2 units/warp
#define ITERS (Dc/128)                   // 24 iters (512B per row per iter)
#define DEPTH 4                          // ring slots per warp
#define RING_WARP_BYTES (DEPTH*2*512)    // 4096 B per warp
#define SMEM_W_BYTES (Kc*Dc*4)           // 122880
#define SMEM_RING_BYTES (WARPS*RING_WARP_BYTES)  // 98304
#define SMEM_BYTES (SMEM_W_BYTES + SMEM_RING_BYTES + 64)  // + bias

typedef unsigned long long u64;

__device__ float g_l1[Bc*Nc];
__device__ float g_l2[Bc*Nc];
__device__ float g_part[Bc];

// ---- packed f32x2 FMA (Blackwell; add/sub/mul/fma only in f32x2) ----
#define FMA2(d, a, b, c) \
    asm("fma.rn.f32x2 %0, %1, %2, %3;" : "=l"(d) : "l"(a), "l"(b), "l"(c))
// scalar saturating add: clip(a+b,0,1) in one FADD.SAT
#define ADDSAT(d, a, b) \
    asm("add.rn.sat.f32 %0, %1, %2;" : "=f"(d) : "f"(a), "f"(b))

#define CP_ASYNC_16(saddr, gaddr) \
    asm volatile("cp.async.cg.shared.global [%0], [%1], 16;" :: "r"(saddr), "l"(gaddr))
#define CP_COMMIT() asm volatile("cp.async.commit_group;")
#define CP_WAIT_1() asm volatile("cp.async.wait_group 1;")

__device__ __forceinline__ u64 pack2(float lo, float hi) {
    u64 r;
    asm("mov.b64 %0, {%1, %2};" : "=l"(r) : "f"(lo), "f"(hi));
    return r;
}
__device__ __forceinline__ void unpack2(float& lo, float& hi, u64 v) {
    asm("mov.b64 {%0, %1}, %2;" : "=f"(lo), "=f"(hi) : "l"(v));
}
__device__ __forceinline__ float4 lds128(unsigned saddr) {
    float4 v;
    asm("ld.shared.v4.f32 {%0,%1,%2,%3}, [%4];"
        : "=f"(v.x), "=f"(v.y), "=f"(v.z), "=f"(v.w) : "r"(saddr));
    return v;
}

__global__ __launch_bounds__(THREADS, 1)
void logits_kernel(const float* __restrict__ imgs,
                   const float* __restrict__ deltas,
                   const float* __restrict__ Wm,
                   const float* __restrict__ bias,
                   const int*   __restrict__ labels)
{
    extern __shared__ float sW[];        // [Kc][Dc] transposed W | ring | bias
    float* sBias = sW + (SMEM_W_BYTES + SMEM_RING_BYTES)/4;

    for (int idx = threadIdx.x; idx < Dc*Kc; idx += THREADS) {
        int d = idx / Kc, k = idx % Kc;
        sW[k*Dc + d] = Wm[idx];
    }
    if (threadIdx.x < Kc) sBias[threadIdx.x] = bias[threadIdx.x];
    __syncthreads();

    const int warp  = threadIdx.x >> 5;
    const int lane  = threadIdx.x & 31;
    const int wslot = blockIdx.x*WARPS + warp;

    unsigned smem_base;
    asm("{ .reg .u64 t; cvta.to.shared.u64 t, %1; cvt.u32.u64 %0, t; }"
        : "=r"(smem_base) : "l"(sW));
    // this lane's 16B slice inside this warp's ring
    const unsigned ring = smem_base + SMEM_W_BYTES + warp*RING_WARP_BYTES + lane*16;

    // 2 units per warp: u and u+3072 share the same b (img row stays warm)
    for (int u = wslot; u < NUNITS; u += WSLOTS) {
        const int b  = u & (Bc-1);
        const int n0 = (u >> 7) * RPW;

        const float4* img4 = (const float4*)(imgs + (size_t)b*Dc) + lane;
        const char* gd0 = (const char*)(deltas + ((size_t)(n0+0)*Bc + b)*Dc) + lane*16;
        const char* gd1 = (const char*)(deltas + ((size_t)(n0+1)*Bc + b)*Dc) + lane*16;
        const ulonglong2* w0 = (const ulonglong2*)sW + lane;

        u64 acc[RPW][Kc];
#pragma unroll
        for (int r = 0; r < RPW; r++)
#pragma unroll
            for (int k = 0; k < Kc; k++) acc[r][k] = 0ULL;

        // prologue: 2 groups in flight
#pragma unroll
        for (int p = 0; p < 2; p++) {
            unsigned s = ring + (p & 3)*1024;
            CP_ASYNC_16(s,       gd0 + p*512);
            CP_ASYNC_16(s + 512, gd1 + p*512);
            CP_COMMIT();
        }

#pragma unroll 1
        for (int i = 0; i < ITERS; i++) {
            CP_WAIT_1();                          // slot i is ready
            const unsigned s = ring + (i & 3)*1024;
            float4 xi  = __ldg(img4 + i*32);
            float4 dd0 = lds128(s);
            float4 dd1 = lds128(s + 512);

            const int ip = i + 2;                 // keep 2 groups in flight
            if (ip < ITERS) {
                unsigned sn = ring + (ip & 3)*1024;
                CP_ASYNC_16(sn,       gd0 + ip*512);
                CP_ASYNC_16(sn + 512, gd1 + ip*512);
            }
            CP_COMMIT();                          // (empty group near tail is fine)

            u64 xp[RPW][2];
            {
                float a0,a1,a2,a3;
                ADDSAT(a0, xi.x, dd0.x); ADDSAT(a1, xi.y, dd0.y);
                ADDSAT(a2, xi.z, dd0.z); ADDSAT(a3, xi.w, dd0.w);
                xp[0][0] = pack2(a0,a1); xp[0][1] = pack2(a2,a3);
            }
            {
                float a0,a1,a2,a3;
                ADDSAT(a0, xi.x, dd1.x); ADDSAT(a1, xi.y, dd1.y);
                ADDSAT(a2, xi.z, dd1.z); ADDSAT(a3, xi.w, dd1.w);
                xp[1][0] = pack2(a0,a1); xp[1][1] = pack2(a2,a3);
            }

            const int e = i*32;
#pragma unroll
            for (int k = 0; k < Kc; k++) {
                ulonglong2 w2 = w0[k*(Dc/4) + e];
                FMA2(acc[0][k], xp[0][0], w2.x, acc[0][k]);
                FMA2(acc[0][k], xp[0][1], w2.y, acc[0][k]);
                FMA2(acc[1][k], xp[1][0], w2.x, acc[1][k]);
                FMA2(acc[1][k], xp[1][1], w2.y, acc[1][k]);
            }
        }

        // Per-row epilogue: warp reduce 10 logits, compute loss1/loss2
#pragma unroll
        for (int r = 0; r < RPW; r++) {
            float lg[Kc];
#pragma unroll
            for (int k = 0; k < Kc; k++) {
                float lo, hi;
                unpack2(lo, hi, acc[r][k]);
                float v = lo + hi;
                v += __shfl_xor_sync(0xFFFFFFFFu, v, 16);
                v += __shfl_xor_sync(0xFFFFFFFFu, v, 8);
                v += __shfl_xor_sync(0xFFFFFFFFu, v, 4);
                v += __shfl_xor_sync(0xFFFFFFFFu, v, 2);
                v += __shfl_xor_sync(0xFFFFFFFFu, v, 1);
                lg[k] = v;
            }
            if (lane == 0) {
#pragma unroll
                for (int k = 0; k < Kc; k++) lg[k] += sBias[k];

                // argmax (first occurrence, matches top_k tie rule)
                float m = lg[0]; int t1 = 0;
#pragma unroll
                for (int k = 1; k < Kc; k++)
                    if (lg[k] > m) { m = lg[k]; t1 = k; }

                float s = 0.0f;
#pragma unroll
                for (int k = 0; k < Kc; k++) s += expf(lg[k] - m);
                float lse = m + logf(s);

                int lab = __ldg(labels + b);
                float logit_lab = lg[0];
#pragma unroll
                for (int k = 1; k < Kc; k++)
                    if (k == lab) logit_lab = lg[k];
                float loss1 = lse - logit_lab;

                // second-best (first occurrence among k != t1)
                float m2 = -INFINITY; int t2 = 0;
#pragma unroll
                for (int k = 0; k < Kc; k++)
                    if (k != t1 && lg[k] > m2) { m2 = lg[k]; t2 = k; }
                float logit_t2 = lg[0];
#pragma unroll
                for (int k = 1; k < Kc; k++)
                    if (k == t2) logit_t2 = lg[k];

                float loss2 = (t1 == lab) ? (lse - logit_t2) : -10000.0f;

                g_l1[b*Nc + (n0 + r)] = loss1;
                g_l2[b*Nc + (n0 + r)] = loss2;
            }
        }
    }
}

// Per-batch-row stable rank-select (replicates stable argsort exactly)
__global__ void select_kernel(const int* __restrict__ indp)
{
    __shared__ float sd[Nc];
    __shared__ float sl1[Nc];
    __shared__ float sSel;

    const int b = blockIdx.x;
    const int j = threadIdx.x;   // 0..95

    float l1v = 0.0f, l2v = 0.0f, dv = 0.0f;
    if (j < Nc) {
        l1v = g_l1[b*Nc + j];
        l2v = g_l2[b*Nc + j];
        dv  = l1v - l2v;
        sd[j]  = dv;
        sl1[j] = l1v;
    }
    __syncthreads();

    const int ind = __ldg(indp);
    if (j < Nc) {
        int cnt = 0;
        for (int i = 0; i < Nc; i++) {
            float di = sd[i];
            cnt += (di < dv) || (di == dv && i < j);
        }
        if (cnt == ind) sSel = l2v;   // exactly one j satisfies this
    }
    __syncthreads();

    if (j == 0) {
        float ssum = 0.0f;
        for (int i = 0; i < Nc; i++) ssum += sl1[i];
        g_part[b] = ssum / (float)Nc - sSel;
    }
}

__global__ void reduce_kernel(float* __restrict__ out)
{
    if (threadIdx.x == 0) {
        float a = 0.0f;
#pragma unroll
        for (int i = 0; i < Bc; i++) a += g_part[i];
        out[0] = a / (float)Bc;
    }
}

extern "C" void kernel_launch(void* const* d_in, const int* in_sizes, int n_in,
                              void* d_out, int out_size)
{
    const float* imgs   = (const float*)d_in[0];
    const float* deltas = (const float*)d_in[1];
    const float* Wm     = (const float*)d_in[2];
    const float* bias   = (const float*)d_in[3];
    const int*   labels = (const int*)d_in[4];
    const int*   indp   = (const int*)d_in[5];
    float* out = (float*)d_out;

    cudaFuncSetAttribute(logits_kernel,
                         cudaFuncAttributeMaxDynamicSharedMemorySize, SMEM_BYTES);

    logits_kernel<<<GRID1, THREADS, SMEM_BYTES>>>(imgs, deltas, Wm, bias, labels);
    select_kernel<<<Bc, Nc>>>(indp);
    reduce_kernel<<<1, 32>>>(out);
}

// round 16
// speedup vs baseline: 1.6318x; 1.0967x over previous
#include <cuda_runtime.h>
#include <math.h>

// Problem constants (fixed by setup_inputs)
#define Bc 128
#define Nc 96
#define Dc 3072
#define Kc 10
#define KP 5                         // k-pairs
#define RPW 3                        // rows per warp-unit
#define WARPS 32
#define THREADS (WARPS*32)           // 1024
#define GRID1 128
#define NUNITS (Bc*(Nc/RPW))         // 4096 == GRID1*WARPS, exactly 1 unit/warp
#define ITERS (Dc/64)                // 48 iters; 64 d's per warp-iter (2 per lane)
#define SMEM_BYTES (KP*Dc*8)         // 122880: W as k-pair u64, [kp][d]

typedef unsigned long long u64;

__device__ float g_l1[Bc*Nc];
__device__ float g_l2[Bc*Nc];
__device__ float g_part[Bc];
__device__ int   g_ticket = 0;

// ---- packed f32x2 FMA (Blackwell) ----
#define FMA2(d, a, b, c) \
    asm("fma.rn.f32x2 %0, %1, %2, %3;" : "=l"(d) : "l"(a), "l"(b), "l"(c))
#define ADD2(d, a, b) \
    asm("add.rn.f32x2 %0, %1, %2;" : "=l"(d) : "l"(a), "l"(b))
// scalar saturating add: clip(a+b,0,1) in one FADD.SAT
#define ADDSAT(d, a, b) \
    asm("add.rn.sat.f32 %0, %1, %2;" : "=f"(d) : "f"(a), "f"(b))

__device__ __forceinline__ u64 dup2(float v) {
    u64 r;
    asm("mov.b64 %0, {%1, %1};" : "=l"(r) : "f"(v));
    return r;
}
__device__ __forceinline__ void unpack2(float& lo, float& hi, u64 v) {
    asm("mov.b64 {%0, %1}, %2;" : "=f"(lo), "=f"(hi) : "l"(v));
}

__global__ __launch_bounds__(THREADS, 1)
void logits_kernel(const float* __restrict__ imgs,
                   const float* __restrict__ deltas,
                   const float* __restrict__ Wm,
                   const float* __restrict__ bias,
                   const int*   __restrict__ labels)
{
    extern __shared__ u64 sW2[];   // [KP][Dc]: sW2[kp*Dc+d] = (W[d][2kp], W[d][2kp+1])

    // W rows are 5 contiguous u64 k-pairs; transpose to kp-major (one-time)
    const u64* Wm64 = (const u64*)Wm;
    for (int idx = threadIdx.x; idx < Dc*KP; idx += THREADS) {
        int d = idx / KP, kp = idx - d*KP;
        sW2[kp*Dc + d] = Wm64[idx];
    }
    __syncthreads();

    const int warp = threadIdx.x >> 5;
    const int lane = threadIdx.x & 31;
    const int u    = blockIdx.x*WARPS + warp;      // 0..4095, exactly one unit
    const int b    = u & (Bc-1);
    const int n0   = (u >> 7) * RPW;

    const float2* img2 = (const float2*)(imgs + (size_t)b*Dc) + lane;
    const float2* dp   = (const float2*)(deltas + ((size_t)n0*Bc + b)*Dc) + lane;
    const ulonglong2* w0 = (const ulonglong2*)sW2 + lane;   // lane's 2-d slice

    u64 acc[RPW*KP];
#pragma unroll
    for (int a = 0; a < RPW*KP; a++) acc[a] = 0ULL;

#pragma unroll 1
    for (int i = 0; i < ITERS; i++) {
        const int e = i*32;                        // float2 index step
        float2 xi  = __ldg(img2 + e);
        float2 dd0 = __ldcs(dp + e);
        float2 dd1 = __ldcs(dp + e + (size_t)Bc*Dc/2);
        float2 dd2 = __ldcs(dp + e + (size_t)Bc*Dc);

        // clip once per (row, d), duplicate into both packed halves
        float a00, a01, a10, a11, a20, a21;
        ADDSAT(a00, xi.x, dd0.x); ADDSAT(a01, xi.y, dd0.y);
        ADDSAT(a10, xi.x, dd1.x); ADDSAT(a11, xi.y, dd1.y);
        ADDSAT(a20, xi.x, dd2.x); ADDSAT(a21, xi.y, dd2.y);
        u64 x00 = dup2(a00), x01 = dup2(a01);
        u64 x10 = dup2(a10), x11 = dup2(a11);
        u64 x20 = dup2(a20), x21 = dup2(a21);

#pragma unroll
        for (int kp = 0; kp < KP; kp++) {
            // (k-pair for d0, k-pair for d1), conflict-free LDS.128
            ulonglong2 w2 = w0[kp*(Dc/2) + e];
            FMA2(acc[0*KP+kp], x00, w2.x, acc[0*KP+kp]);
            FMA2(acc[0*KP+kp], x01, w2.y, acc[0*KP+kp]);
            FMA2(acc[1*KP+kp], x10, w2.x, acc[1*KP+kp]);
            FMA2(acc[1*KP+kp], x11, w2.y, acc[1*KP+kp]);
            FMA2(acc[2*KP+kp], x20, w2.x, acc[2*KP+kp]);
            FMA2(acc[2*KP+kp], x21, w2.y, acc[2*KP+kp]);
        }
    }

    // Epilogue: full packed butterfly per (row, kp), then scalar losses
#pragma unroll
    for (int r = 0; r < RPW; r++) {
        u64 s[KP];
#pragma unroll
        for (int kp = 0; kp < KP; kp++) {
            u64 v = acc[r*KP+kp];
#pragma unroll
            for (int m = 16; m >= 1; m >>= 1) {
                u64 o = __shfl_xor_sync(0xFFFFFFFFu, v, m);
                ADD2(v, v, o);
            }
            s[kp] = v;
        }
        if (lane == 0) {
            float lg[Kc];
#pragma unroll
            for (int kp = 0; kp < KP; kp++) {
                float lo, hi;
                unpack2(lo, hi, s[kp]);
                lg[2*kp]   = lo + __ldg(bias + 2*kp);
                lg[2*kp+1] = hi + __ldg(bias + 2*kp+1);
            }

            // argmax (first occurrence, matches top_k tie rule)
            float m = lg[0]; int t1 = 0;
#pragma unroll
            for (int k = 1; k < Kc; k++)
                if (lg[k] > m) { m = lg[k]; t1 = k; }

            float sum = 0.0f;
#pragma unroll
            for (int k = 0; k < Kc; k++) sum += expf(lg[k] - m);
            float lse = m + logf(sum);

            int lab = __ldg(labels + b);
            float logit_lab = lg[0];
#pragma unroll
            for (int k = 1; k < Kc; k++)
                if (k == lab) logit_lab = lg[k];
            float loss1 = lse - logit_lab;

            float m2 = -INFINITY; int t2 = 0;
#pragma unroll
            for (int k = 0; k < Kc; k++)
                if (k != t1 && lg[k] > m2) { m2 = lg[k]; t2 = k; }
            float logit_t2 = lg[0];
#pragma unroll
            for (int k = 1; k < Kc; k++)
                if (k == t2) logit_t2 = lg[k];

            float loss2 = (t1 == lab) ? (lse - logit_t2) : -10000.0f;

            g_l1[b*Nc + (n0 + r)] = loss1;
            g_l2[b*Nc + (n0 + r)] = loss2;
        }
    }
}

// Per-batch stable rank-select; last block also does the final mean (ticket).
__global__ void select_kernel(const int* __restrict__ indp,
                              float* __restrict__ out)
{
    __shared__ float sd[Nc];
    __shared__ float sl1[Nc];
    __shared__ float sSel;

    const int b = blockIdx.x;
    const int j = threadIdx.x;   // 0..95

    float l1v = 0.0f, l2v = 0.0f, dv = 0.0f;
    if (j < Nc) {
        l1v = g_l1[b*Nc + j];
        l2v = g_l2[b*Nc + j];
        dv  = l1v - l2v;
        sd[j]  = dv;
        sl1[j] = l1v;
    }
    __syncthreads();

    const int ind = __ldg(indp);
    if (j < Nc) {
        int cnt = 0;
        for (int i = 0; i < Nc; i++) {
            float di = sd[i];
            cnt += (di < dv) || (di == dv && i < j);
        }
        if (cnt == ind) sSel = l2v;   // exactly one j satisfies this
    }
    __syncthreads();

    if (j == 0) {
        float ssum = 0.0f;
        for (int i = 0; i < Nc; i++) ssum += sl1[i];
        g_part[b] = ssum / (float)Nc - sSel;
        __threadfence();
        int t = atomicAdd(&g_ticket, 1);
        if (t == Bc - 1) {            // last block: reduce + reset ticket
            __threadfence();
            float a = 0.0f;
#pragma unroll
            for (int i = 0; i < Bc; i++) a += g_part[i];
            out[0] = a / (float)Bc;
            g_ticket = 0;             // deterministic state for graph replay
        }
    }
}

extern "C" void kernel_launch(void* const* d_in, const int* in_sizes, int n_in,
                              void* d_out, int out_size)
{
    const float* imgs   = (const float*)d_in[0];
    const float* deltas = (const float*)d_in[1];
    const float* Wm     = (const float*)d_in[2];
    const float* bias   = (const float*)d_in[3];
    const int*   labels = (const int*)d_in[4];
    const int*   indp   = (const int*)d_in[5];
    float* out = (float*)d_out;

    cudaFuncSetAttribute(logits_kernel,
                         cudaFuncAttributeMaxDynamicSharedMemorySize, SMEM_BYTES);

    logits_kernel<<<GRID1, THREADS, SMEM_BYTES>>>(imgs, deltas, Wm, bias, labels);
    select_kernel<<<Bc, Nc>>>(indp, out);
}